// round 2
// baseline (speedup 1.0000x reference)
#include <cuda_runtime.h>

// Deform_Conv_V1: fused offset-conv + deformable conv + ReLU.
// B=8, Cin=32, H=W=160, Cout=32, K=3, PAD=1.
// Inputs: x (8,32,160,160), w_off (18,32,3,3), b_off (18,), w_dcn (32,32,3,3)
// Output: (8,32,160,160) fp32.
//
// R2: 2 adjacent pixels per thread (halves warp-uniform weight LDS per pixel),
//     w_off smem padded to 20 floats/row -> float4 LDS, float2 output stores.

#define Hn  160
#define Wn  160
#define CIN 32
#define COUT 32
#define HWs (Hn * Wn)

__global__ __launch_bounds__(128)
void dcn_fused_kernel(const float* __restrict__ x,
                      const float* __restrict__ w_off,
                      const float* __restrict__ b_off,
                      const float* __restrict__ w_dcn,
                      float* __restrict__ out)
{
    extern __shared__ float smem[];
    float* w_dcn_s = smem;               // [9][32][32]  (k, c, o)  : 9216 floats
    float* w_off_s = smem + 9 * 32 * 32; // [9][32][20]  (k, c, oc) : 5760 floats (oc 18,19 = 0)

    const int tid = threadIdx.x;

    // Stage weights transposed into shared memory.
    for (int i = tid; i < 9 * 32 * 32; i += 128) {
        int k = i >> 10;
        int r = i & 1023;
        int c = r >> 5;
        int o = r & 31;
        w_dcn_s[i] = w_dcn[o * 288 + c * 9 + k];
    }
    for (int i = tid; i < 9 * 32 * 20; i += 128) {
        int k = i / 640;
        int r = i - k * 640;
        int c = r / 20;
        int oc = r - c * 20;
        w_off_s[i] = (oc < 18) ? w_off[oc * 288 + c * 9 + k] : 0.0f;
    }
    __syncthreads();

    // Each thread owns pixel pair (h, 2*wp) and (h, 2*wp+1).
    const int pairIdx = blockIdx.x * 128 + tid;      // 0 .. 102399
    const int PAIRS_PER_IMG = HWs / 2;               // 12800
    const int b   = pairIdx / PAIRS_PER_IMG;
    const int rem = pairIdx - b * PAIRS_PER_IMG;
    const int h   = rem / (Wn / 2);
    const int w0  = (rem - h * (Wn / 2)) * 2;        // even; w1 = w0+1
    const float* xb = x + (size_t)b * CIN * HWs;

    // ---------------- Stage 1: offset conv, both pixels ----------------
    float offs0[20], offs1[20];
#pragma unroll
    for (int j = 0; j < 18; j++) {
        float bv = __ldg(&b_off[j]);
        offs0[j] = bv; offs1[j] = bv;
    }
    offs0[18] = offs0[19] = offs1[18] = offs1[19] = 0.0f;

#pragma unroll 1
    for (int k = 0; k < 9; k++) {
        const int ky = k / 3;
        const int kx = k - 3 * ky;
        const int yy  = h - 1 + ky;
        if (yy < 0 || yy >= Hn) continue;
        const int xx0 = w0 - 1 + kx;
        const int xx1 = xx0 + 1;
        const bool v0 = (xx0 >= 0) && (xx0 < Wn);
        const bool v1 = (xx1 >= 0) && (xx1 < Wn);
        const float* xr = xb + yy * Wn;
        const float4* wp4 = (const float4*)(w_off_s + k * 32 * 20);
#pragma unroll 4
        for (int c = 0; c < CIN; c++) {
            const float xv0 = v0 ? __ldg(xr + c * HWs + xx0) : 0.0f;
            const float xv1 = v1 ? __ldg(xr + c * HWs + xx1) : 0.0f;
#pragma unroll
            for (int j = 0; j < 5; j++) {
                float4 q = wp4[c * 5 + j];
                offs0[4*j+0] += xv0 * q.x;  offs1[4*j+0] += xv1 * q.x;
                offs0[4*j+1] += xv0 * q.y;  offs1[4*j+1] += xv1 * q.y;
                offs0[4*j+2] += xv0 * q.z;  offs1[4*j+2] += xv1 * q.z;
                offs0[4*j+3] += xv0 * q.w;  offs1[4*j+3] += xv1 * q.w;
            }
        }
    }

    // ---------------- Stage 2: deformable conv, both pixels ----------------
    float acc0[32], acc1[32];
#pragma unroll
    for (int o = 0; o < 32; o++) { acc0[o] = 0.0f; acc1[o] = 0.0f; }

#pragma unroll 1
    for (int k = 0; k < 9; k++) {
        const int ky = k / 3;
        const int kx = k - 3 * ky;

        // --- corner data, pixel 0 ---
        float pw00, pw01, pw10, pw11; int p00, p01, p10, p11;
        {
            const float py = (float)(h - 1 + ky) + offs0[2*k];
            const float px = (float)(w0 - 1 + kx) + offs0[2*k+1];
            const float y0f = floorf(py), x0f = floorf(px);
            const float wy1 = py - y0f, wx1 = px - x0f;
            const float wy0 = 1.0f - wy1, wx0 = 1.0f - wx1;
            const float y1f = y0f + 1.0f, x1f = x0f + 1.0f;
            const bool vy0 = (y0f >= 0.0f) && (y0f <= (float)(Hn-1));
            const bool vy1 = (y1f >= 0.0f) && (y1f <= (float)(Hn-1));
            const bool vx0 = (x0f >= 0.0f) && (x0f <= (float)(Wn-1));
            const bool vx1 = (x1f >= 0.0f) && (x1f <= (float)(Wn-1));
            pw00 = (vy0 && vx0) ? wy0*wx0 : 0.0f;
            pw01 = (vy0 && vx1) ? wy0*wx1 : 0.0f;
            pw10 = (vy1 && vx0) ? wy1*wx0 : 0.0f;
            pw11 = (vy1 && vx1) ? wy1*wx1 : 0.0f;
            const int iy0 = min(max((int)y0f, 0), Hn-1);
            const int iy1 = min(max((int)y1f, 0), Hn-1);
            const int ix0 = min(max((int)x0f, 0), Wn-1);
            const int ix1 = min(max((int)x1f, 0), Wn-1);
            p00 = iy0*Wn + ix0; p01 = iy0*Wn + ix1;
            p10 = iy1*Wn + ix0; p11 = iy1*Wn + ix1;
        }
        // --- corner data, pixel 1 ---
        float qw00, qw01, qw10, qw11; int q00, q01, q10, q11;
        {
            const float py = (float)(h - 1 + ky) + offs1[2*k];
            const float px = (float)(w0 + kx) + offs1[2*k+1];
            const float y0f = floorf(py), x0f = floorf(px);
            const float wy1 = py - y0f, wx1 = px - x0f;
            const float wy0 = 1.0f - wy1, wx0 = 1.0f - wx1;
            const float y1f = y0f + 1.0f, x1f = x0f + 1.0f;
            const bool vy0 = (y0f >= 0.0f) && (y0f <= (float)(Hn-1));
            const bool vy1 = (y1f >= 0.0f) && (y1f <= (float)(Hn-1));
            const bool vx0 = (x0f >= 0.0f) && (x0f <= (float)(Wn-1));
            const bool vx1 = (x1f >= 0.0f) && (x1f <= (float)(Wn-1));
            qw00 = (vy0 && vx0) ? wy0*wx0 : 0.0f;
            qw01 = (vy0 && vx1) ? wy0*wx1 : 0.0f;
            qw10 = (vy1 && vx0) ? wy1*wx0 : 0.0f;
            qw11 = (vy1 && vx1) ? wy1*wx1 : 0.0f;
            const int iy0 = min(max((int)y0f, 0), Hn-1);
            const int iy1 = min(max((int)y1f, 0), Hn-1);
            const int ix0 = min(max((int)x0f, 0), Wn-1);
            const int ix1 = min(max((int)x1f, 0), Wn-1);
            q00 = iy0*Wn + ix0; q01 = iy0*Wn + ix1;
            q10 = iy1*Wn + ix0; q11 = iy1*Wn + ix1;
        }

        const float4* wp4 = (const float4*)(w_dcn_s + k * 32 * 32);
#pragma unroll 4
        for (int c = 0; c < CIN; c++) {
            const float* xc = xb + c * HWs;
            const float val0 = pw00 * __ldg(xc + p00) + pw01 * __ldg(xc + p01)
                             + pw10 * __ldg(xc + p10) + pw11 * __ldg(xc + p11);
            const float val1 = qw00 * __ldg(xc + q00) + qw01 * __ldg(xc + q01)
                             + qw10 * __ldg(xc + q10) + qw11 * __ldg(xc + q11);
#pragma unroll
            for (int j = 0; j < 8; j++) {
                float4 q = wp4[c * 8 + j];
                acc0[4*j+0] += val0 * q.x;  acc1[4*j+0] += val1 * q.x;
                acc0[4*j+1] += val0 * q.y;  acc1[4*j+1] += val1 * q.y;
                acc0[4*j+2] += val0 * q.z;  acc1[4*j+2] += val1 * q.z;
                acc0[4*j+3] += val0 * q.w;  acc1[4*j+3] += val1 * q.w;
            }
        }
    }

    // ---------------- Epilogue: ReLU + coalesced float2 stores ----------------
    float* ob = out + (size_t)b * COUT * HWs + h * Wn + w0;
#pragma unroll
    for (int o = 0; o < 32; o++) {
        float2 r;
        r.x = fmaxf(acc0[o], 0.0f);
        r.y = fmaxf(acc1[o], 0.0f);
        *(float2*)(ob + o * HWs) = r;
    }
}

extern "C" void kernel_launch(void* const* d_in, const int* in_sizes, int n_in,
                              void* d_out, int out_size)
{
    const float* x     = (const float*)d_in[0];
    const float* w_off = (const float*)d_in[1];
    const float* b_off = (const float*)d_in[2];
    const float* w_dcn = (const float*)d_in[3];
    float* out = (float*)d_out;

    const int smem_bytes = (9 * 32 * 32 + 9 * 32 * 20) * sizeof(float); // 59904 B
    cudaFuncSetAttribute(dcn_fused_kernel,
                         cudaFuncAttributeMaxDynamicSharedMemorySize, smem_bytes);

    const int total_pairs = 8 * HWs / 2;        // 102400
    const int threads = 128;
    const int blocks = total_pairs / threads;   // 800
    dcn_fused_kernel<<<blocks, threads, smem_bytes>>>(x, w_off, b_off, w_dcn, out);
}

// round 3
// speedup vs baseline: 2.5124x; 2.5124x over previous
#include <cuda_runtime.h>

// Deform_Conv_V1: fused offset-conv + deformable conv + ReLU.
// B=8, Cin=32, H=W=160, Cout=32, K=3, PAD=1.
// Inputs: x (8,32,160,160), w_off (18,32,3,3), b_off (18,), w_dcn (32,32,3,3)
// Output: (8,32,160,160) fp32.
//
// R3: 1 pixel/thread; BOTH 9-tap loops fully unrolled so offset/acc state is
//     pure registers (R1/R2 had dynamically-indexed arrays spilled to local
//     memory); packed fma.rn.f32x2 halves FMA-pipe instruction count.

#define Hn  160
#define Wn  160
#define CIN 32
#define COUT 32
#define HWs (Hn * Wn)

typedef unsigned long long u64;

__device__ __forceinline__ u64 pack2(float a, float b) {
    u64 r;
    asm("mov.b64 %0, {%1, %2};" : "=l"(r) : "f"(a), "f"(b));
    return r;
}
__device__ __forceinline__ void unpack2(u64 v, float& a, float& b) {
    asm("mov.b64 {%0, %1}, %2;" : "=f"(a), "=f"(b) : "l"(v));
}
// d = a*b + d  (two fp32 lanes)
__device__ __forceinline__ void ffma2(u64& d, u64 a, u64 b) {
    asm("fma.rn.f32x2 %0, %1, %2, %0;" : "+l"(d) : "l"(a), "l"(b));
}

__global__ __launch_bounds__(256, 2)
void dcn_fused_kernel(const float* __restrict__ x,
                      const float* __restrict__ w_off,
                      const float* __restrict__ b_off,
                      const float* __restrict__ w_dcn,
                      float* __restrict__ out)
{
    extern __shared__ float smem[];
    float* w_dcn_s = smem;               // [9][32][32] (k, c, o)  : 9216 floats
    float* w_off_s = smem + 9 * 32 * 32; // [9][32][20] (k, c, oc) : 5760 floats (oc 18,19 = 0)

    const int tid = threadIdx.x;

    for (int i = tid; i < 9 * 32 * 32; i += 256) {
        int k = i >> 10;
        int r = i & 1023;
        int c = r >> 5;
        int o = r & 31;
        w_dcn_s[i] = w_dcn[o * 288 + c * 9 + k];
    }
    for (int i = tid; i < 9 * 32 * 20; i += 256) {
        int k = i / 640;
        int r = i - k * 640;
        int c = r / 18;   // NOTE: c computed from padded row below
        (void)c;
        int cc = r / 20;
        int oc = r - cc * 20;
        w_off_s[i] = (oc < 18) ? w_off[oc * 288 + cc * 9 + k] : 0.0f;
    }
    __syncthreads();

    const int pix = blockIdx.x * 256 + tid;   // 0 .. 204799
    const int b  = pix / HWs;
    const int hw = pix - b * HWs;
    const int h  = hw / Wn;
    const int w  = hw - h * Wn;
    const float* xb = x + (size_t)b * CIN * HWs;

    // ------------- Stage 1: offset conv, packed accumulators -------------
    // offs2[p] holds (channel 2p, channel 2p+1) = (dy_p, dx_p) for p < 9.
    u64 offs2[10];
#pragma unroll
    for (int p = 0; p < 9; p++)
        offs2[p] = pack2(__ldg(&b_off[2 * p]), __ldg(&b_off[2 * p + 1]));
    offs2[9] = 0ULL;

#pragma unroll
    for (int k = 0; k < 9; k++) {
        const int ky = k / 3;
        const int kx = k - 3 * ky;
        const int yy = h - 1 + ky;
        const int xx = w - 1 + kx;
        if (yy >= 0 && yy < Hn && xx >= 0 && xx < Wn) {
            const float* xp = xb + yy * Wn + xx;
            const ulonglong2* wp = (const ulonglong2*)(w_off_s + k * 640);
#pragma unroll 4
            for (int c = 0; c < CIN; c++) {
                const float xv = __ldg(xp + c * HWs);
                const u64 xv2 = pack2(xv, xv);
                const ulonglong2* wc = wp + c * 5;  // 5 x 16B = 20 floats
#pragma unroll
                for (int j = 0; j < 5; j++) {
                    ulonglong2 q = wc[j];
                    ffma2(offs2[2 * j],     xv2, q.x);
                    ffma2(offs2[2 * j + 1], xv2, q.y);
                }
            }
        }
    }

    // ------------- Stage 2: deformable conv, packed accumulators -------------
    u64 acc2[16];
#pragma unroll
    for (int m = 0; m < 16; m++) acc2[m] = 0ULL;

#pragma unroll
    for (int k = 0; k < 9; k++) {
        const int ky = k / 3;
        const int kx = k - 3 * ky;
        float dy, dx;
        unpack2(offs2[k], dy, dx);           // static index: stays in registers
        const float py = (float)(h - 1 + ky) + dy;
        const float px = (float)(w - 1 + kx) + dx;

        const float y0f = floorf(py), x0f = floorf(px);
        const float wy1 = py - y0f,  wx1 = px - x0f;
        const float wy0 = 1.0f - wy1, wx0 = 1.0f - wx1;
        const float y1f = y0f + 1.0f, x1f = x0f + 1.0f;

        const bool vy0 = (y0f >= 0.0f) && (y0f <= (float)(Hn - 1));
        const bool vy1 = (y1f >= 0.0f) && (y1f <= (float)(Hn - 1));
        const bool vx0 = (x0f >= 0.0f) && (x0f <= (float)(Wn - 1));
        const bool vx1 = (x1f >= 0.0f) && (x1f <= (float)(Wn - 1));

        const float w00 = (vy0 && vx0) ? wy0 * wx0 : 0.0f;
        const float w01 = (vy0 && vx1) ? wy0 * wx1 : 0.0f;
        const float w10 = (vy1 && vx0) ? wy1 * wx0 : 0.0f;
        const float w11 = (vy1 && vx1) ? wy1 * wx1 : 0.0f;

        const int iy0 = min(max((int)y0f, 0), Hn - 1);
        const int iy1 = min(max((int)y1f, 0), Hn - 1);
        const int ix0 = min(max((int)x0f, 0), Wn - 1);
        const int ix1 = min(max((int)x1f, 0), Wn - 1);
        const int i00 = iy0 * Wn + ix0;
        const int i01 = iy0 * Wn + ix1;
        const int i10 = iy1 * Wn + ix0;
        const int i11 = iy1 * Wn + ix1;

        const ulonglong2* wp = (const ulonglong2*)(w_dcn_s + k * 32 * 32);
#pragma unroll 4
        for (int c = 0; c < CIN; c++) {
            const float* xc = xb + c * HWs;
            const float val = fmaf(w00, __ldg(xc + i00),
                             fmaf(w01, __ldg(xc + i01),
                             fmaf(w10, __ldg(xc + i10),
                                  w11 * __ldg(xc + i11))));
            const u64 vv = pack2(val, val);
            const ulonglong2* wc = wp + c * 8;   // 8 x 16B = 32 floats
#pragma unroll
            for (int j = 0; j < 8; j++) {
                ulonglong2 q = wc[j];
                ffma2(acc2[2 * j],     vv, q.x);
                ffma2(acc2[2 * j + 1], vv, q.y);
            }
        }
    }

    // ------------- Epilogue: ReLU + store -------------
    float* ob = out + (size_t)b * COUT * HWs + hw;
#pragma unroll
    for (int m = 0; m < 16; m++) {
        float a, bv;
        unpack2(acc2[m], a, bv);
        ob[(2 * m)     * HWs] = fmaxf(a, 0.0f);
        ob[(2 * m + 1) * HWs] = fmaxf(bv, 0.0f);
    }
}

extern "C" void kernel_launch(void* const* d_in, const int* in_sizes, int n_in,
                              void* d_out, int out_size)
{
    const float* x     = (const float*)d_in[0];
    const float* w_off = (const float*)d_in[1];
    const float* b_off = (const float*)d_in[2];
    const float* w_dcn = (const float*)d_in[3];
    float* out = (float*)d_out;

    const int smem_bytes = (9 * 32 * 32 + 9 * 32 * 20) * sizeof(float); // 59904 B
    cudaFuncSetAttribute(dcn_fused_kernel,
                         cudaFuncAttributeMaxDynamicSharedMemorySize, smem_bytes);

    const int total_pix = 8 * HWs;            // 204800
    const int threads = 256;
    const int blocks = total_pix / threads;   // 800
    dcn_fused_kernel<<<blocks, threads, smem_bytes>>>(x, w_off, b_off, w_dcn, out);
}

// round 5
// speedup vs baseline: 3.0337x; 1.2075x over previous
#include <cuda_runtime.h>

// Deform_Conv_V1: fused offset-conv + deformable conv + ReLU.
// B=8, Cin=32, H=W=160, Cout=32, K=3, PAD=1.
// Inputs: x (8,32,160,160), w_off (18,32,3,3), b_off (18,), w_dcn (32,32,3,3)
// Output: (8,32,160,160) fp32.
//
// R5: R4 (weights in __constant__ memory) with the symbol-address bug fixed:
//     the D2D source must be resolved via cudaGetSymbolAddress, not the
//     host-side shadow of the __device__ symbol.

#define Hn  160
#define Wn  160
#define CIN 32
#define COUT 32
#define HWs (Hn * Wn)

#define WDCN_T_ELEMS (9 * 32 * 32)   // [k][c][o]            = 9216
#define WOFF_T_ELEMS (9 * 32 * 20)   // [k][c][oc pad 20]    = 5760

__constant__ float c_wdcn[WDCN_T_ELEMS];   // 36 KB
__constant__ float c_woff[WOFF_T_ELEMS];   // 22.5 KB
__device__ float g_stage[WDCN_T_ELEMS + WOFF_T_ELEMS];

typedef unsigned long long u64;

__device__ __forceinline__ u64 pack2(float a, float b) {
    u64 r;
    asm("mov.b64 %0, {%1, %2};" : "=l"(r) : "f"(a), "f"(b));
    return r;
}
__device__ __forceinline__ void unpack2(u64 v, float& a, float& b) {
    asm("mov.b64 {%0, %1}, %2;" : "=f"(a), "=f"(b) : "l"(v));
}
__device__ __forceinline__ void ffma2(u64& d, u64 a, u64 b) {
    asm("fma.rn.f32x2 %0, %1, %2, %0;" : "+l"(d) : "l"(a), "l"(b));
}

__global__ void prep_kernel(const float* __restrict__ w_off,
                            const float* __restrict__ w_dcn)
{
    const int i = blockIdx.x * 256 + threadIdx.x;
    if (i < WDCN_T_ELEMS) {
        int k = i >> 10;
        int r = i & 1023;
        int c = r >> 5;
        int o = r & 31;
        g_stage[i] = w_dcn[o * 288 + c * 9 + k];
    }
    if (i < WOFF_T_ELEMS) {
        int k = i / 640;
        int r = i - k * 640;
        int c = r / 20;
        int oc = r - c * 20;
        g_stage[WDCN_T_ELEMS + i] = (oc < 18) ? w_off[oc * 288 + c * 9 + k] : 0.0f;
    }
}

__global__ __launch_bounds__(256, 2)
void dcn_fused_kernel(const float* __restrict__ x,
                      const float* __restrict__ b_off,
                      float* __restrict__ out)
{
    const int pix = blockIdx.x * 256 + threadIdx.x;   // 0 .. 204799
    const int b  = pix / HWs;
    const int hw = pix - b * HWs;
    const int h  = hw / Wn;
    const int w  = hw - h * Wn;
    const float* xb = x + (size_t)b * CIN * HWs;

    // ------------- Stage 1: offset conv, packed accumulators -------------
    u64 offs2[9];
#pragma unroll
    for (int p = 0; p < 9; p++)
        offs2[p] = pack2(__ldg(&b_off[2 * p]), __ldg(&b_off[2 * p + 1]));

#pragma unroll
    for (int k = 0; k < 9; k++) {
        const int ky = k / 3;
        const int kx = k - 3 * ky;
        const int yy = h - 1 + ky;
        const int xx = w - 1 + kx;
        if (yy >= 0 && yy < Hn && xx >= 0 && xx < Wn) {
            const float* xp = xb + yy * Wn + xx;
            const ulonglong2* wp = (const ulonglong2*)(c_woff + k * 640);
#pragma unroll 4
            for (int c = 0; c < CIN; c++) {
                const float xv = __ldg(xp + c * HWs);
                const u64 xv2 = pack2(xv, xv);
                const ulonglong2* wc = wp + c * 5;   // 20 floats per (k,c)
#pragma unroll
                for (int j = 0; j < 4; j++) {        // channels 0..15
                    ulonglong2 q = wc[j];
                    ffma2(offs2[2 * j],     xv2, q.x);
                    ffma2(offs2[2 * j + 1], xv2, q.y);
                }
                ulonglong2 q4 = wc[4];               // channels 16,17 (+2 pad)
                ffma2(offs2[8], xv2, q4.x);
            }
        }
    }

    // ------------- Stage 2: deformable conv, packed accumulators -------------
    u64 acc2[16];
#pragma unroll
    for (int m = 0; m < 16; m++) acc2[m] = 0ULL;

#pragma unroll
    for (int k = 0; k < 9; k++) {
        const int ky = k / 3;
        const int kx = k - 3 * ky;
        float dy, dx;
        unpack2(offs2[k], dy, dx);
        const float py = (float)(h - 1 + ky) + dy;
        const float px = (float)(w - 1 + kx) + dx;

        const float y0f = floorf(py), x0f = floorf(px);
        const float wy1 = py - y0f,  wx1 = px - x0f;
        const float wy0 = 1.0f - wy1, wx0 = 1.0f - wx1;
        const float y1f = y0f + 1.0f, x1f = x0f + 1.0f;

        const bool vy0 = (y0f >= 0.0f) && (y0f <= (float)(Hn - 1));
        const bool vy1 = (y1f >= 0.0f) && (y1f <= (float)(Hn - 1));
        const bool vx0 = (x0f >= 0.0f) && (x0f <= (float)(Wn - 1));
        const bool vx1 = (x1f >= 0.0f) && (x1f <= (float)(Wn - 1));

        const float w00 = (vy0 && vx0) ? wy0 * wx0 : 0.0f;
        const float w01 = (vy0 && vx1) ? wy0 * wx1 : 0.0f;
        const float w10 = (vy1 && vx0) ? wy1 * wx0 : 0.0f;
        const float w11 = (vy1 && vx1) ? wy1 * wx1 : 0.0f;

        const int iy0 = min(max((int)y0f, 0), Hn - 1);
        const int iy1 = min(max((int)y1f, 0), Hn - 1);
        const int ix0 = min(max((int)x0f, 0), Wn - 1);
        const int ix1 = min(max((int)x1f, 0), Wn - 1);
        const int i00 = iy0 * Wn + ix0;
        const int i01 = iy0 * Wn + ix1;
        const int i10 = iy1 * Wn + ix0;
        const int i11 = iy1 * Wn + ix1;

        const ulonglong2* wp = (const ulonglong2*)(c_wdcn + k * 1024);
#pragma unroll 4
        for (int c = 0; c < CIN; c++) {
            const float* xc = xb + c * HWs;
            const float val = fmaf(w00, __ldg(xc + i00),
                             fmaf(w01, __ldg(xc + i01),
                             fmaf(w10, __ldg(xc + i10),
                                  w11 * __ldg(xc + i11))));
            const u64 vv = pack2(val, val);
            const ulonglong2* wc = wp + c * 8;   // 32 floats per (k,c)
#pragma unroll
            for (int j = 0; j < 8; j++) {
                ulonglong2 q = wc[j];
                ffma2(acc2[2 * j],     vv, q.x);
                ffma2(acc2[2 * j + 1], vv, q.y);
            }
        }
    }

    // ------------- Epilogue: ReLU + store -------------
    float* ob = out + (size_t)b * COUT * HWs + hw;
#pragma unroll
    for (int m = 0; m < 16; m++) {
        float a, bv;
        unpack2(acc2[m], a, bv);
        ob[(2 * m)     * HWs] = fmaxf(a, 0.0f);
        ob[(2 * m + 1) * HWs] = fmaxf(bv, 0.0f);
    }
}

extern "C" void kernel_launch(void* const* d_in, const int* in_sizes, int n_in,
                              void* d_out, int out_size)
{
    const float* x     = (const float*)d_in[0];
    const float* w_off = (const float*)d_in[1];
    const float* b_off = (const float*)d_in[2];
    const float* w_dcn = (const float*)d_in[3];
    float* out = (float*)d_out;

    // Resolve the true device address of the staging symbol (query only).
    void* stage_dev = nullptr;
    cudaGetSymbolAddress(&stage_dev, g_stage);

    // 1) transpose weights into staging layout
    prep_kernel<<<(WDCN_T_ELEMS + 255) / 256, 256>>>(w_off, w_dcn);

    // 2) stage -> constant memory (device-to-device async copies; capturable)
    cudaMemcpyToSymbolAsync(c_wdcn, stage_dev,
                            WDCN_T_ELEMS * sizeof(float), 0,
                            cudaMemcpyDeviceToDevice, 0);
    cudaMemcpyToSymbolAsync(c_woff, (const char*)stage_dev + WDCN_T_ELEMS * sizeof(float),
                            WOFF_T_ELEMS * sizeof(float), 0,
                            cudaMemcpyDeviceToDevice, 0);

    // 3) fused kernel
    const int total_pix = 8 * HWs;            // 204800
    const int threads = 256;
    const int blocks = total_pix / threads;   // 800
    dcn_fused_kernel<<<blocks, threads>>>(x, b_off, out);
}

// round 6
// speedup vs baseline: 3.4669x; 1.1428x over previous
#include <cuda_runtime.h>

// Deform_Conv_V1: fused offset-conv + deformable conv + ReLU.
// B=8, Cin=32, H=W=160, Cout=32, K=3, PAD=1.
// Inputs: x (8,32,160,160), w_off (18,32,3,3), b_off (18,), w_dcn (32,32,3,3)
// Output: (8,32,160,160) fp32.
//
// R6: weights in __constant__ memory (R5) + 2 adjacent pixels per thread so
//     each LDC.128 (constant-port floor = 8 cyc, the R5 binder) feeds twice
//     the FFMA2 work. Fully-unrolled k loops keep all state in registers.

#define Hn  160
#define Wn  160
#define CIN 32
#define COUT 32
#define HWs (Hn * Wn)

#define WDCN_T_ELEMS (9 * 32 * 32)   // [k][c][o]         = 9216
#define WOFF_T_ELEMS (9 * 32 * 20)   // [k][c][oc pad 20] = 5760

__constant__ float c_wdcn[WDCN_T_ELEMS];   // 36 KB
__constant__ float c_woff[WOFF_T_ELEMS];   // 22.5 KB
__device__ float g_stage[WDCN_T_ELEMS + WOFF_T_ELEMS];

typedef unsigned long long u64;

__device__ __forceinline__ u64 pack2(float a, float b) {
    u64 r;
    asm("mov.b64 %0, {%1, %2};" : "=l"(r) : "f"(a), "f"(b));
    return r;
}
__device__ __forceinline__ void unpack2(u64 v, float& a, float& b) {
    asm("mov.b64 {%0, %1}, %2;" : "=f"(a), "=f"(b) : "l"(v));
}
__device__ __forceinline__ void ffma2(u64& d, u64 a, u64 b) {
    asm("fma.rn.f32x2 %0, %1, %2, %0;" : "+l"(d) : "l"(a), "l"(b));
}

__global__ void prep_kernel(const float* __restrict__ w_off,
                            const float* __restrict__ w_dcn)
{
    const int i = blockIdx.x * 256 + threadIdx.x;
    if (i < WDCN_T_ELEMS) {
        int k = i >> 10;
        int r = i & 1023;
        int c = r >> 5;
        int o = r & 31;
        g_stage[i] = w_dcn[o * 288 + c * 9 + k];
    }
    if (i < WOFF_T_ELEMS) {
        int k = i / 640;
        int r = i - k * 640;
        int c = r / 20;
        int oc = r - c * 20;
        g_stage[WDCN_T_ELEMS + i] = (oc < 18) ? w_off[oc * 288 + c * 9 + k] : 0.0f;
    }
}

__global__ __launch_bounds__(128, 3)
void dcn_fused_kernel(const float* __restrict__ x,
                      const float* __restrict__ b_off,
                      float* __restrict__ out)
{
    // Each thread owns pixel pair (h, w0) and (h, w0+1), w0 even.
    const int pairIdx = blockIdx.x * 128 + threadIdx.x;   // 0 .. 102399
    const int PAIRS_PER_IMG = HWs / 2;                    // 12800
    const int b   = pairIdx / PAIRS_PER_IMG;
    const int rem = pairIdx - b * PAIRS_PER_IMG;
    const int h   = rem / (Wn / 2);
    const int w0  = (rem - h * (Wn / 2)) * 2;
    const float* xb = x + (size_t)b * CIN * HWs;

    // ------------- Stage 1: offset conv, packed accumulators, both pixels -------------
    u64 o2a[9], o2b[9];
#pragma unroll
    for (int p = 0; p < 9; p++) {
        u64 bv = pack2(__ldg(&b_off[2 * p]), __ldg(&b_off[2 * p + 1]));
        o2a[p] = bv;
        o2b[p] = bv;
    }

#pragma unroll
    for (int k = 0; k < 9; k++) {
        const int ky = k / 3;
        const int kx = k - 3 * ky;
        const int yy = h - 1 + ky;
        if (yy >= 0 && yy < Hn) {
            const int xx0 = w0 - 1 + kx;
            const int xx1 = xx0 + 1;
            const bool v0 = (xx0 >= 0) && (xx0 < Wn);
            const bool v1 = (xx1 >= 0) && (xx1 < Wn);
            const float* xr = xb + yy * Wn;
            const ulonglong2* wp = (const ulonglong2*)(c_woff + k * 640);
#pragma unroll 4
            for (int c = 0; c < CIN; c++) {
                const float xv0 = v0 ? __ldg(xr + c * HWs + xx0) : 0.0f;
                const float xv1 = v1 ? __ldg(xr + c * HWs + xx1) : 0.0f;
                const u64 xa = pack2(xv0, xv0);
                const u64 xbv = pack2(xv1, xv1);
                const ulonglong2* wc = wp + c * 5;    // 20 floats per (k,c)
#pragma unroll
                for (int j = 0; j < 4; j++) {         // channels 0..15
                    ulonglong2 q = wc[j];
                    ffma2(o2a[2 * j],     xa,  q.x);
                    ffma2(o2a[2 * j + 1], xa,  q.y);
                    ffma2(o2b[2 * j],     xbv, q.x);
                    ffma2(o2b[2 * j + 1], xbv, q.y);
                }
                ulonglong2 q4 = wc[4];                // channels 16,17 (+2 pad)
                ffma2(o2a[8], xa,  q4.x);
                ffma2(o2b[8], xbv, q4.x);
            }
        }
    }

    // ------------- Stage 2: deformable conv, packed accumulators, both pixels -------------
    u64 acca[16], accb[16];
#pragma unroll
    for (int m = 0; m < 16; m++) { acca[m] = 0ULL; accb[m] = 0ULL; }

#pragma unroll
    for (int k = 0; k < 9; k++) {
        const int ky = k / 3;
        const int kx = k - 3 * ky;

        // corner weights/indices, pixel A
        float aw00, aw01, aw10, aw11; int a00, a01, a10, a11;
        {
            float dy, dx; unpack2(o2a[k], dy, dx);
            const float py = (float)(h - 1 + ky) + dy;
            const float px = (float)(w0 - 1 + kx) + dx;
            const float y0f = floorf(py), x0f = floorf(px);
            const float wy1 = py - y0f,  wx1 = px - x0f;
            const float wy0 = 1.0f - wy1, wx0 = 1.0f - wx1;
            const float y1f = y0f + 1.0f, x1f = x0f + 1.0f;
            const bool vy0 = (y0f >= 0.0f) && (y0f <= (float)(Hn - 1));
            const bool vy1 = (y1f >= 0.0f) && (y1f <= (float)(Hn - 1));
            const bool vx0 = (x0f >= 0.0f) && (x0f <= (float)(Wn - 1));
            const bool vx1 = (x1f >= 0.0f) && (x1f <= (float)(Wn - 1));
            aw00 = (vy0 && vx0) ? wy0 * wx0 : 0.0f;
            aw01 = (vy0 && vx1) ? wy0 * wx1 : 0.0f;
            aw10 = (vy1 && vx0) ? wy1 * wx0 : 0.0f;
            aw11 = (vy1 && vx1) ? wy1 * wx1 : 0.0f;
            const int iy0 = min(max((int)y0f, 0), Hn - 1);
            const int iy1 = min(max((int)y1f, 0), Hn - 1);
            const int ix0 = min(max((int)x0f, 0), Wn - 1);
            const int ix1 = min(max((int)x1f, 0), Wn - 1);
            a00 = iy0 * Wn + ix0; a01 = iy0 * Wn + ix1;
            a10 = iy1 * Wn + ix0; a11 = iy1 * Wn + ix1;
        }
        // corner weights/indices, pixel B
        float bw00, bw01, bw10, bw11; int b00, b01, b10, b11;
        {
            float dy, dx; unpack2(o2b[k], dy, dx);
            const float py = (float)(h - 1 + ky) + dy;
            const float px = (float)(w0 + kx) + dx;
            const float y0f = floorf(py), x0f = floorf(px);
            const float wy1 = py - y0f,  wx1 = px - x0f;
            const float wy0 = 1.0f - wy1, wx0 = 1.0f - wx1;
            const float y1f = y0f + 1.0f, x1f = x0f + 1.0f;
            const bool vy0 = (y0f >= 0.0f) && (y0f <= (float)(Hn - 1));
            const bool vy1 = (y1f >= 0.0f) && (y1f <= (float)(Hn - 1));
            const bool vx0 = (x0f >= 0.0f) && (x0f <= (float)(Wn - 1));
            const bool vx1 = (x1f >= 0.0f) && (x1f <= (float)(Wn - 1));
            bw00 = (vy0 && vx0) ? wy0 * wx0 : 0.0f;
            bw01 = (vy0 && vx1) ? wy0 * wx1 : 0.0f;
            bw10 = (vy1 && vx0) ? wy1 * wx0 : 0.0f;
            bw11 = (vy1 && vx1) ? wy1 * wx1 : 0.0f;
            const int iy0 = min(max((int)y0f, 0), Hn - 1);
            const int iy1 = min(max((int)y1f, 0), Hn - 1);
            const int ix0 = min(max((int)x0f, 0), Wn - 1);
            const int ix1 = min(max((int)x1f, 0), Wn - 1);
            b00 = iy0 * Wn + ix0; b01 = iy0 * Wn + ix1;
            b10 = iy1 * Wn + ix0; b11 = iy1 * Wn + ix1;
        }

        const ulonglong2* wp = (const ulonglong2*)(c_wdcn + k * 1024);
#pragma unroll 4
        for (int c = 0; c < CIN; c++) {
            const float* xc = xb + c * HWs;
            const float va = fmaf(aw00, __ldg(xc + a00),
                            fmaf(aw01, __ldg(xc + a01),
                            fmaf(aw10, __ldg(xc + a10),
                                 aw11 * __ldg(xc + a11))));
            const float vb = fmaf(bw00, __ldg(xc + b00),
                            fmaf(bw01, __ldg(xc + b01),
                            fmaf(bw10, __ldg(xc + b10),
                                 bw11 * __ldg(xc + b11))));
            const u64 va2 = pack2(va, va);
            const u64 vb2 = pack2(vb, vb);
            const ulonglong2* wc = wp + c * 8;   // 32 floats per (k,c)
#pragma unroll
            for (int j = 0; j < 8; j++) {
                ulonglong2 q = wc[j];
                ffma2(acca[2 * j],     va2, q.x);
                ffma2(acca[2 * j + 1], va2, q.y);
                ffma2(accb[2 * j],     vb2, q.x);
                ffma2(accb[2 * j + 1], vb2, q.y);
            }
        }
    }

    // ------------- Epilogue: ReLU + coalesced float2 stores -------------
    float* ob = out + (size_t)b * COUT * HWs + h * Wn + w0;
#pragma unroll
    for (int m = 0; m < 16; m++) {
        float a0, a1, c0, c1;
        unpack2(acca[m], a0, a1);
        unpack2(accb[m], c0, c1);
        float2 r0, r1;
        r0.x = fmaxf(a0, 0.0f); r0.y = fmaxf(c0, 0.0f);
        r1.x = fmaxf(a1, 0.0f); r1.y = fmaxf(c1, 0.0f);
        *(float2*)(ob + (2 * m)     * HWs) = r0;
        *(float2*)(ob + (2 * m + 1) * HWs) = r1;
    }
}

extern "C" void kernel_launch(void* const* d_in, const int* in_sizes, int n_in,
                              void* d_out, int out_size)
{
    const float* x     = (const float*)d_in[0];
    const float* w_off = (const float*)d_in[1];
    const float* b_off = (const float*)d_in[2];
    const float* w_dcn = (const float*)d_in[3];
    float* out = (float*)d_out;

    void* stage_dev = nullptr;
    cudaGetSymbolAddress(&stage_dev, g_stage);

    prep_kernel<<<(WDCN_T_ELEMS + 255) / 256, 256>>>(w_off, w_dcn);

    cudaMemcpyToSymbolAsync(c_wdcn, stage_dev,
                            WDCN_T_ELEMS * sizeof(float), 0,
                            cudaMemcpyDeviceToDevice, 0);
    cudaMemcpyToSymbolAsync(c_woff, (const char*)stage_dev + WDCN_T_ELEMS * sizeof(float),
                            WOFF_T_ELEMS * sizeof(float), 0,
                            cudaMemcpyDeviceToDevice, 0);

    const int total_pairs = 8 * HWs / 2;        // 102400
    const int threads = 128;
    const int blocks = total_pairs / threads;   // 800
    dcn_fused_kernel<<<blocks, threads>>>(x, b_off, out);
}

// round 7
// speedup vs baseline: 3.5427x; 1.0219x over previous
#include <cuda_runtime.h>

// Deform_Conv_V1: fused offset-conv + deformable conv + ReLU.
// B=8, Cin=32, H=W=160, Cout=32, K=3, PAD=1.
// Inputs: x (8,32,160,160), w_off (18,32,3,3), b_off (18,), w_dcn (32,32,3,3)
// Output: (8,32,160,160) fp32.
//
// R7: R6 (constants + 2px/thread + FFMA2) with occupancy push:
//     - offsets stashed in thread-private smem between stages (frees 36 regs)
//     - __launch_bounds__(128,4) -> 128 regs -> 4 CTAs/SM (16 warps)
//     - bilinear packed across the two pixels (8 FMA -> 4 FFMA2 per (k,c))

#define Hn  160
#define Wn  160
#define CIN 32
#define COUT 32
#define HWs (Hn * Wn)

#define WDCN_T_ELEMS (9 * 32 * 32)   // [k][c][o]         = 9216
#define WOFF_T_ELEMS (9 * 32 * 20)   // [k][c][oc pad 20] = 5760

__constant__ float c_wdcn[WDCN_T_ELEMS];   // 36 KB
__constant__ float c_woff[WOFF_T_ELEMS];   // 22.5 KB
__device__ float g_stage[WDCN_T_ELEMS + WOFF_T_ELEMS];

typedef unsigned long long u64;

__device__ __forceinline__ u64 pack2(float a, float b) {
    u64 r;
    asm("mov.b64 %0, {%1, %2};" : "=l"(r) : "f"(a), "f"(b));
    return r;
}
__device__ __forceinline__ void unpack2(u64 v, float& a, float& b) {
    asm("mov.b64 {%0, %1}, %2;" : "=f"(a), "=f"(b) : "l"(v));
}
__device__ __forceinline__ void ffma2(u64& d, u64 a, u64 b) {
    asm("fma.rn.f32x2 %0, %1, %2, %0;" : "+l"(d) : "l"(a), "l"(b));
}

__global__ void prep_kernel(const float* __restrict__ w_off,
                            const float* __restrict__ w_dcn)
{
    const int i = blockIdx.x * 256 + threadIdx.x;
    if (i < WDCN_T_ELEMS) {
        int k = i >> 10;
        int r = i & 1023;
        int c = r >> 5;
        int o = r & 31;
        g_stage[i] = w_dcn[o * 288 + c * 9 + k];
    }
    if (i < WOFF_T_ELEMS) {
        int k = i / 640;
        int r = i - k * 640;
        int c = r / 20;
        int oc = r - c * 20;
        g_stage[WDCN_T_ELEMS + i] = (oc < 18) ? w_off[oc * 288 + c * 9 + k] : 0.0f;
    }
}

__global__ __launch_bounds__(128, 4)
void dcn_fused_kernel(const float* __restrict__ x,
                      const float* __restrict__ b_off,
                      float* __restrict__ out)
{
    // Thread-private offset stash: same thread writes then reads -> no syncs.
    __shared__ u64 offs_s[2][128][9];   // 18432 B/CTA

    const int tid = threadIdx.x;
    const int pairIdx = blockIdx.x * 128 + tid;   // 0 .. 102399
    const int PAIRS_PER_IMG = HWs / 2;            // 12800
    const int b   = pairIdx / PAIRS_PER_IMG;
    const int rem = pairIdx - b * PAIRS_PER_IMG;
    const int h   = rem / (Wn / 2);
    const int w0  = (rem - h * (Wn / 2)) * 2;
    const float* xb = x + (size_t)b * CIN * HWs;

    // ------------- Stage 1: offset conv, packed accumulators, both pixels -------------
    {
        u64 o2a[9], o2b[9];
#pragma unroll
        for (int p = 0; p < 9; p++) {
            u64 bv = pack2(__ldg(&b_off[2 * p]), __ldg(&b_off[2 * p + 1]));
            o2a[p] = bv;
            o2b[p] = bv;
        }

#pragma unroll
        for (int k = 0; k < 9; k++) {
            const int ky = k / 3;
            const int kx = k - 3 * ky;
            const int yy = h - 1 + ky;
            if (yy >= 0 && yy < Hn) {
                const int xx0 = w0 - 1 + kx;
                const int xx1 = xx0 + 1;
                const bool v0 = (xx0 >= 0) && (xx0 < Wn);
                const bool v1 = (xx1 >= 0) && (xx1 < Wn);
                const float* xr = xb + yy * Wn;
                const ulonglong2* wp = (const ulonglong2*)(c_woff + k * 640);
#pragma unroll 4
                for (int c = 0; c < CIN; c++) {
                    const float xv0 = v0 ? __ldg(xr + c * HWs + xx0) : 0.0f;
                    const float xv1 = v1 ? __ldg(xr + c * HWs + xx1) : 0.0f;
                    const u64 xa  = pack2(xv0, xv0);
                    const u64 xbv = pack2(xv1, xv1);
                    const ulonglong2* wc = wp + c * 5;
#pragma unroll
                    for (int j = 0; j < 4; j++) {
                        ulonglong2 q = wc[j];
                        ffma2(o2a[2 * j],     xa,  q.x);
                        ffma2(o2a[2 * j + 1], xa,  q.y);
                        ffma2(o2b[2 * j],     xbv, q.x);
                        ffma2(o2b[2 * j + 1], xbv, q.y);
                    }
                    ulonglong2 q4 = wc[4];
                    ffma2(o2a[8], xa,  q4.x);
                    ffma2(o2b[8], xbv, q4.x);
                }
            }
        }

        // Stash offsets: frees these 36 registers for stage 2.
#pragma unroll
        for (int p = 0; p < 9; p++) {
            offs_s[0][tid][p] = o2a[p];
            offs_s[1][tid][p] = o2b[p];
        }
    }

    // ------------- Stage 2: deformable conv, packed accumulators, both pixels -------------
    u64 acca[16], accb[16];
#pragma unroll
    for (int m = 0; m < 16; m++) { acca[m] = 0ULL; accb[m] = 0ULL; }

#pragma unroll
    for (int k = 0; k < 9; k++) {
        const int ky = k / 3;
        const int kx = k - 3 * ky;

        // corner weights/indices, pixel A
        float aw00, aw01, aw10, aw11; int a00, a01, a10, a11;
        {
            float dy, dx; unpack2(offs_s[0][tid][k], dy, dx);
            const float py = (float)(h - 1 + ky) + dy;
            const float px = (float)(w0 - 1 + kx) + dx;
            const float y0f = floorf(py), x0f = floorf(px);
            const float wy1 = py - y0f,  wx1 = px - x0f;
            const float wy0 = 1.0f - wy1, wx0 = 1.0f - wx1;
            const float y1f = y0f + 1.0f, x1f = x0f + 1.0f;
            const bool vy0 = (y0f >= 0.0f) && (y0f <= (float)(Hn - 1));
            const bool vy1 = (y1f >= 0.0f) && (y1f <= (float)(Hn - 1));
            const bool vx0 = (x0f >= 0.0f) && (x0f <= (float)(Wn - 1));
            const bool vx1 = (x1f >= 0.0f) && (x1f <= (float)(Wn - 1));
            aw00 = (vy0 && vx0) ? wy0 * wx0 : 0.0f;
            aw01 = (vy0 && vx1) ? wy0 * wx1 : 0.0f;
            aw10 = (vy1 && vx0) ? wy1 * wx0 : 0.0f;
            aw11 = (vy1 && vx1) ? wy1 * wx1 : 0.0f;
            const int iy0 = min(max((int)y0f, 0), Hn - 1);
            const int iy1 = min(max((int)y1f, 0), Hn - 1);
            const int ix0 = min(max((int)x0f, 0), Wn - 1);
            const int ix1 = min(max((int)x1f, 0), Wn - 1);
            a00 = iy0 * Wn + ix0; a01 = iy0 * Wn + ix1;
            a10 = iy1 * Wn + ix0; a11 = iy1 * Wn + ix1;
        }
        // corner weights/indices, pixel B
        float bw00, bw01, bw10, bw11; int b00, b01, b10, b11;
        {
            float dy, dx; unpack2(offs_s[1][tid][k], dy, dx);
            const float py = (float)(h - 1 + ky) + dy;
            const float px = (float)(w0 + kx) + dx;
            const float y0f = floorf(py), x0f = floorf(px);
            const float wy1 = py - y0f,  wx1 = px - x0f;
            const float wy0 = 1.0f - wy1, wx0 = 1.0f - wx1;
            const float y1f = y0f + 1.0f, x1f = x0f + 1.0f;
            const bool vy0 = (y0f >= 0.0f) && (y0f <= (float)(Hn - 1));
            const bool vy1 = (y1f >= 0.0f) && (y1f <= (float)(Hn - 1));
            const bool vx0 = (x0f >= 0.0f) && (x0f <= (float)(Wn - 1));
            const bool vx1 = (x1f >= 0.0f) && (x1f <= (float)(Wn - 1));
            bw00 = (vy0 && vx0) ? wy0 * wx0 : 0.0f;
            bw01 = (vy0 && vx1) ? wy0 * wx1 : 0.0f;
            bw10 = (vy1 && vx0) ? wy1 * wx0 : 0.0f;
            bw11 = (vy1 && vx1) ? wy1 * wx1 : 0.0f;
            const int iy0 = min(max((int)y0f, 0), Hn - 1);
            const int iy1 = min(max((int)y1f, 0), Hn - 1);
            const int ix0 = min(max((int)x0f, 0), Wn - 1);
            const int ix1 = min(max((int)x1f, 0), Wn - 1);
            b00 = iy0 * Wn + ix0; b01 = iy0 * Wn + ix1;
            b10 = iy1 * Wn + ix0; b11 = iy1 * Wn + ix1;
        }

        // packed (pixelA, pixelB) corner weights
        const u64 W00 = pack2(aw00, bw00);
        const u64 W01 = pack2(aw01, bw01);
        const u64 W10 = pack2(aw10, bw10);
        const u64 W11 = pack2(aw11, bw11);

        const ulonglong2* wp = (const ulonglong2*)(c_wdcn + k * 1024);
#pragma unroll 4
        for (int c = 0; c < CIN; c++) {
            const float* xc = xb + c * HWs;
            const u64 P00 = pack2(__ldg(xc + a00), __ldg(xc + b00));
            const u64 P01 = pack2(__ldg(xc + a01), __ldg(xc + b01));
            const u64 P10 = pack2(__ldg(xc + a10), __ldg(xc + b10));
            const u64 P11 = pack2(__ldg(xc + a11), __ldg(xc + b11));
            u64 vab = 0ULL;
            ffma2(vab, W00, P00);
            ffma2(vab, W01, P01);
            ffma2(vab, W10, P10);
            ffma2(vab, W11, P11);
            float va, vb; unpack2(vab, va, vb);
            const u64 va2 = pack2(va, va);
            const u64 vb2 = pack2(vb, vb);
            const ulonglong2* wc = wp + c * 8;
#pragma unroll
            for (int j = 0; j < 8; j++) {
                ulonglong2 q = wc[j];
                ffma2(acca[2 * j],     va2, q.x);
                ffma2(acca[2 * j + 1], va2, q.y);
                ffma2(accb[2 * j],     vb2, q.x);
                ffma2(accb[2 * j + 1], vb2, q.y);
            }
        }
    }

    // ------------- Epilogue: ReLU + coalesced float2 stores -------------
    float* ob = out + (size_t)b * COUT * HWs + h * Wn + w0;
#pragma unroll
    for (int m = 0; m < 16; m++) {
        float a0, a1, c0, c1;
        unpack2(acca[m], a0, a1);
        unpack2(accb[m], c0, c1);
        float2 r0, r1;
        r0.x = fmaxf(a0, 0.0f); r0.y = fmaxf(c0, 0.0f);
        r1.x = fmaxf(a1, 0.0f); r1.y = fmaxf(c1, 0.0f);
        *(float2*)(ob + (2 * m)     * HWs) = r0;
        *(float2*)(ob + (2 * m + 1) * HWs) = r1;
    }
}

extern "C" void kernel_launch(void* const* d_in, const int* in_sizes, int n_in,
                              void* d_out, int out_size)
{
    const float* x     = (const float*)d_in[0];
    const float* w_off = (const float*)d_in[1];
    const float* b_off = (const float*)d_in[2];
    const float* w_dcn = (const float*)d_in[3];
    float* out = (float*)d_out;

    void* stage_dev = nullptr;
    cudaGetSymbolAddress(&stage_dev, g_stage);

    prep_kernel<<<(WDCN_T_ELEMS + 255) / 256, 256>>>(w_off, w_dcn);

    cudaMemcpyToSymbolAsync(c_wdcn, stage_dev,
                            WDCN_T_ELEMS * sizeof(float), 0,
                            cudaMemcpyDeviceToDevice, 0);
    cudaMemcpyToSymbolAsync(c_woff, (const char*)stage_dev + WDCN_T_ELEMS * sizeof(float),
                            WOFF_T_ELEMS * sizeof(float), 0,
                            cudaMemcpyDeviceToDevice, 0);

    const int total_pairs = 8 * HWs / 2;        // 102400
    const int threads = 128;
    const int blocks = total_pairs / threads;   // 800
    dcn_fused_kernel<<<blocks, threads>>>(x, b_off, out);
}